// round 3
// baseline (speedup 1.0000x reference)
#include <cuda_runtime.h>
#include <math.h>

#define BB 4
#define HH 544
#define WW 960
#define H2 272
#define W2 480
#define MD 24

// ---------------- scratch (no allocations allowed) ----------------
__device__ float g_lg[BB * H2 * W2];
__device__ float g_rg[BB * H2 * W2];
__device__ float g_nd[BB * H2 * W2];
__device__ float g_nc[BB * H2 * W2];
// accumulators padded to one 128B line each to avoid LTS atomic serialization
// idx: 0 gtNum 1 gtDen 2 photoNum 3 photoDen 4 signSum 5 magSum 6 activeSum 7 smx 8 smy
__device__ double g_acc[9 * 16];

// ---------------- helpers ----------------
__device__ __forceinline__ float blockReduceSum(float v, float* sbuf) {
    int tid = threadIdx.x + threadIdx.y * blockDim.x;
    int lane = tid & 31, wid = tid >> 5;
#pragma unroll
    for (int o = 16; o > 0; o >>= 1) v += __shfl_down_sync(0xffffffffu, v, o);
    if (lane == 0) sbuf[wid] = v;
    __syncthreads();
    int nw = (blockDim.x * blockDim.y + 31) >> 5;
    v = (tid < nw) ? sbuf[tid] : 0.f;
    if (wid == 0) {
#pragma unroll
        for (int o = 16; o > 0; o >>= 1) v += __shfl_down_sync(0xffffffffu, v, o);
    }
    __syncthreads();
    return v;  // valid at tid 0
}

// ---------------- kernels ----------------
// half-res grayscale + accumulator zeroing (block 0)
__global__ void downsample_kernel(const float* __restrict__ left,
                                  const float* __restrict__ right) {
    if (blockIdx.x == 0 && threadIdx.x < 9 * 16) g_acc[threadIdx.x] = 0.0;
    int i = blockIdx.x * blockDim.x + threadIdx.x;
    const int NPAIR = W2 / 2;  // 240
    if (i >= BB * H2 * NPAIR) return;
    int px = i % NPAIR;
    int y = (i / NPAIR) % H2;
    int b = i / (NPAIR * H2);
    float l0 = 0.f, l1 = 0.f, r0 = 0.f, r1 = 0.f;
#pragma unroll
    for (int c = 0; c < 3; c++) {
        int base = ((b * 3 + c) * HH + 2 * y) * WW + 4 * px;
        float4 a0 = *(const float4*)(left + base);
        float4 a1 = *(const float4*)(left + base + WW);
        l0 += (a0.x + a0.y + a1.x + a1.y);
        l1 += (a0.z + a0.w + a1.z + a1.w);
        float4 b0 = *(const float4*)(right + base);
        float4 b1 = *(const float4*)(right + base + WW);
        r0 += (b0.x + b0.y + b1.x + b1.y);
        r1 += (b0.z + b0.w + b1.z + b1.w);
    }
    const float S = 0.25f / 3.0f;
    int o = (b * H2 + y) * W2 + 2 * px;
    *(float2*)(g_lg + o) = make_float2(l0 * S, l1 * S);
    *(float2*)(g_rg + o) = make_float2(r0 * S, r1 * S);
}

// NCC disparity search: one CTA per (b, half-res row), 160 threads x 3 columns.
// Disparities in register groups of 6; rg window of 8 serves 18 FMAs.
__global__ __launch_bounds__(160) void ncc_kernel() {
    __shared__ float rgS[11][528];            // rg rows, zero-padded +/-24 (idx = x+24)
    __shared__ float crp[560], cr2p[560];     // rg column sums (idx = x+40), zero pads
    __shared__ float HcrS[528], Hcr2S[528];   // 11-box of cr at u=idx-24
    __shared__ float ccPool[6 * 492];         // per-dj cross column sums (idx = x+5)
    float* clp = ccPool;                      // setup-only aliases (560 each)
    float* cl2p = ccPool + 560;
    const float NORM = 1.0f / 121.0f;

    int row = blockIdx.x;
    int b = row / H2;
    int y = row - b * H2;
    int t = threadIdx.x;
    int x0 = t * 3;
    const float* lgB = g_lg + b * H2 * W2;
    const float* rgB = g_rg + b * H2 * W2;

    float lgR[11][3];
    float cr[3] = {0, 0, 0}, cr2[3] = {0, 0, 0}, cl[3] = {0, 0, 0}, cl2[3] = {0, 0, 0};
#pragma unroll
    for (int r = 0; r < 11; r++) {
        int yy = y + r - 5;
        bool vy = (yy >= 0 && yy < H2);
#pragma unroll
        for (int j = 0; j < 3; j++) {
            float lv = 0.f, rv = 0.f;
            if (vy) { lv = lgB[yy * W2 + x0 + j]; rv = rgB[yy * W2 + x0 + j]; }
            lgR[r][j] = lv;
            rgS[r][x0 + j + 24] = rv;
            cr[j] += rv; cr2[j] += rv * rv;
            cl[j] += lv; cl2[j] += lv * lv;
        }
        if (t < 8) {
#pragma unroll
            for (int j = 0; j < 3; j++) {
                rgS[r][t * 3 + j] = 0.f;          // left pad 0..23
                rgS[r][504 + t * 3 + j] = 0.f;    // right pad 504..527
            }
        }
    }
#pragma unroll
    for (int j = 0; j < 3; j++) {
        crp[x0 + j + 40] = cr[j];  cr2p[x0 + j + 40] = cr2[j];
        clp[x0 + j + 40] = cl[j];  cl2p[x0 + j + 40] = cl2[j];
    }
    if (t < 40) { crp[t] = 0.f; cr2p[t] = 0.f; clp[t] = 0.f; cl2p[t] = 0.f; }
    if (t >= 120) { crp[400 + t] = 0.f; cr2p[400 + t] = 0.f; clp[400 + t] = 0.f; cl2p[400 + t] = 0.f; }
    __syncthreads();

    // Hcr[i] = 11-box of cr column sums centered at col i-24 : taps crp[i+11..i+21]
    for (int i = t; i < 528; i += 160) {
        float s = 0.f, s2 = 0.f;
#pragma unroll
        for (int k = 0; k < 11; k++) { s += crp[i + 11 + k]; s2 += cr2p[i + 11 + k]; }
        HcrS[i] = s; Hcr2S[i] = s2;
    }

    // left stats per column (sliding over 3 cols)
    float lm[3], ls[3];
    {
        float b0 = clp[x0 + 35], b1 = clp[x0 + 36];
        float m0 = b0 + b1;
#pragma unroll
        for (int k = 2; k < 11; k++) m0 += clp[x0 + 35 + k];
        float m1 = m0 - b0 + clp[x0 + 46];
        float m2 = m1 - b1 + clp[x0 + 47];
        float c0 = cl2p[x0 + 35], c1 = cl2p[x0 + 36];
        float q0 = c0 + c1;
#pragma unroll
        for (int k = 2; k < 11; k++) q0 += cl2p[x0 + 35 + k];
        float q1 = q0 - c0 + cl2p[x0 + 46];
        float q2 = q1 - c1 + cl2p[x0 + 47];
        float mm[3] = {m0, m1, m2}, qq[3] = {q0, q1, q2};
#pragma unroll
        for (int j = 0; j < 3; j++) {
            float m = mm[j] * NORM, q = qq[j] * NORM;
            lm[j] = m;
            ls[j] = sqrtf(fmaxf(q - m * m, 1e-8f));
        }
    }
    __syncthreads();

    // zero ccS pads (overwrites clp/cl2p region; visible after first group sync)
#pragma unroll
    for (int g = 0; g < 6; g++) {
        float* cs = ccPool + g * 492;
        if (t < 5) cs[t] = 0.f;
        if (t >= 153) cs[332 + t] = 0.f;   // 485..491
    }

    float bestC[3] = {-1.f, -1.f, -1.f};
    float bestD[3] = {0.f, 0.f, 0.f};
    bool inter[3];
#pragma unroll
    for (int j = 0; j < 3; j++) inter[j] = (x0 + j >= 5 && x0 + j < 475);

    for (int g = 0; g < 8; g++) {
        int d0 = (g < 4) ? (6 * g - 24) : (6 * g - 23);
        float cc[3][6];
#pragma unroll
        for (int j = 0; j < 3; j++)
#pragma unroll
            for (int dj = 0; dj < 6; dj++) cc[j][dj] = 0.f;
        int ub = x0 + d0 + 24;
#pragma unroll
        for (int r = 0; r < 11; r++) {
            float w[8];
#pragma unroll
            for (int i = 0; i < 8; i++) w[i] = rgS[r][ub + i];
#pragma unroll
            for (int j = 0; j < 3; j++) {
                float lv = lgR[r][j];
#pragma unroll
                for (int dj = 0; dj < 6; dj++) cc[j][dj] += lv * w[j + dj];
            }
        }
#pragma unroll
        for (int dj = 0; dj < 6; dj++) {
            float* cs = ccPool + dj * 492;
#pragma unroll
            for (int j = 0; j < 3; j++) cs[x0 + j + 5] = cc[j][dj];
        }
        __syncthreads();
#pragma unroll
        for (int dj = 0; dj < 6; dj++) {
            int d = d0 + dj;
            const float* cs = ccPool + dj * 492;
            float a0 = cs[x0], a1 = cs[x0 + 1], a2 = cs[x0 + 2], a3 = cs[x0 + 3], a4 = cs[x0 + 4];
            float a8 = cs[x0 + 8], a9 = cs[x0 + 9], a10 = cs[x0 + 10];
            float w0 = cc[0][dj] + cc[1][dj] + cc[2][dj] + a0 + a1 + a2 + a3 + a4 + a8 + a9 + a10;
            float a11 = cs[x0 + 11], a12 = cs[x0 + 12];
            float w1 = w0 - a0 + a11;
            float w2 = w1 - a1 + a12;
            float cw[3] = {w0, w1, w2};
#pragma unroll
            for (int j = 0; j < 3; j++) {
                int xj = x0 + j;
                float rm121, r2121;
                if (inter[j]) {
                    rm121 = HcrS[xj + d + 24];
                    r2121 = Hcr2S[xj + d + 24];
                } else {
                    rm121 = 0.f; r2121 = 0.f;
#pragma unroll
                    for (int k = -5; k <= 5; k++) {
                        int u = xj + k;
                        if (u >= 0 && u < W2) {
                            rm121 += crp[u + d + 40];
                            r2121 += cr2p[u + d + 40];
                        }
                    }
                }
                float rm = rm121 * NORM;
                float rstd = sqrtf(fmaxf(r2121 * NORM - rm * rm, 1e-8f));
                float ncc = (cw[j] * NORM - lm[j] * rm) / (ls[j] * rstd + 1e-8f);
                if (ncc > bestC[j]) { bestC[j] = ncc; bestD[j] = (float)d; }
            }
        }
        __syncthreads();
    }
    int o = (b * H2 + y) * W2 + x0;
#pragma unroll
    for (int j = 0; j < 3; j++) {
        g_nd[o + j] = bestD[j] * 2.0f;
        g_nc[o + j] = fmaxf(bestC[j], 0.f);
    }
}

// ONE fused full-res pass: warp-on-the-fly + SSIM/L1 photometric + GT anchor
// + smoothness + sign/magnitude. 64x8 tiles, 128 threads, 4 outputs/thread.
__global__ __launch_bounds__(128) void tile_kernel(const float* __restrict__ pred,
                                                   const float* __restrict__ gt,
                                                   const float* __restrict__ conf,
                                                   const float* __restrict__ occ,
                                                   const float* __restrict__ left,
                                                   const float* __restrict__ right) {
    __shared__ float lS[3][10][66];
    __shared__ float wS[3][10][66];
    __shared__ float dS[10][66];
    __shared__ float sbuf[8];
    int b = blockIdx.z;
    int tx0 = blockIdx.x * 64, ty0 = blockIdx.y * 8;
    int tid = threadIdx.y * 16 + threadIdx.x;

    // halo load: compute warped right on the fly
    for (int i = tid; i < 10 * 66; i += 128) {
        int col = i % 66;
        int rrow = i / 66;
        int gx = tx0 + col - 1, gy = ty0 + rrow - 1;
        if (gx >= 0 && gx < WW && gy >= 0 && gy < HH) {
            float disp = pred[(b * HH + gy) * WW + gx];
            dS[rrow][col] = disp;
            float xs = (float)gx - disp;
            float xc = fminf(fmaxf(xs, 0.f), (float)(WW - 1));
            float x0f = floorf(xc);
            float w = xc - x0f;
            int x0i = (int)x0f;
            int x1i = min(x0i + 1, WW - 1);
#pragma unroll
            for (int c = 0; c < 3; c++) {
                const float* R = right + ((b * 3 + c) * HH + gy) * WW;
                wS[c][rrow][col] = R[x0i] * (1.f - w) + R[x1i] * w;
                lS[c][rrow][col] = left[((b * 3 + c) * HH + gy) * WW + gx];
            }
        } else {
            dS[rrow][col] = 0.f;
#pragma unroll
            for (int c = 0; c < 3; c++) { wS[c][rrow][col] = 0.f; lS[c][rrow][col] = 0.f; }
        }
    }
    __syncthreads();

    int tx = threadIdx.x, ty = threadIdx.y;
    int lx0 = 4 * tx;                 // local col of first output
    int gx0 = tx0 + lx0, gy = ty0 + ty;

    float ssAcc[4] = {0, 0, 0, 0}, l1Acc[4] = {0, 0, 0, 0};
    float sidx[4] = {0, 0, 0, 0}, sidy[4] = {0, 0, 0, 0};
    const float N9 = 1.f / 9.f;
    const float C1 = 1e-4f, C2 = 9e-4f;
#pragma unroll
    for (int c = 0; c < 3; c++) {
        float win[4][5];
#pragma unroll
        for (int j = 0; j < 4; j++)
#pragma unroll
            for (int q = 0; q < 5; q++) win[j][q] = 0.f;
        float prev1 = 0.f;
#pragma unroll
        for (int u = 0; u < 6; u++) {
            float l0 = lS[c][ty][lx0 + u], l1 = lS[c][ty + 1][lx0 + u], l2 = lS[c][ty + 2][lx0 + u];
            float m0 = wS[c][ty][lx0 + u], m1 = wS[c][ty + 1][lx0 + u], m2 = wS[c][ty + 2][lx0 + u];
            float cA = l0 + l1 + l2;
            float cB = m0 + m1 + m2;
            float cC = l0 * l0 + l1 * l1 + l2 * l2;
            float cD = m0 * m0 + m1 * m1 + m2 * m2;
            float cE = l0 * m0 + l1 * m1 + l2 * m2;
#pragma unroll
            for (int j = 0; j < 4; j++) {
                if (u >= j && u <= j + 2) {
                    win[j][0] += cA; win[j][1] += cB; win[j][2] += cC;
                    win[j][3] += cD; win[j][4] += cE;
                }
            }
            if (u >= 1 && u <= 4) {
                l1Acc[u - 1] += fabsf(l1 - m1);
                sidy[u - 1] += fabsf(l2 - l1);
            }
            if (u >= 2) sidx[u - 2] += fabsf(l1 - prev1);
            prev1 = l1;
        }
#pragma unroll
        for (int j = 0; j < 4; j++) {
            float mx = win[j][0] * N9, my = win[j][1] * N9;
            float vx = fmaxf(win[j][2] * N9 - mx * mx, 0.f);
            float vy = fmaxf(win[j][3] * N9 - my * my, 0.f);
            float cxy = win[j][4] * N9 - mx * my;
            float nn = (2.f * mx * my + C1) * (2.f * cxy + C2);
            float dd = (mx * mx + my * my + C1) * (vx + vy + C2);
            ssAcc[j] += fminf(fmaxf((1.f - nn / dd) * 0.5f, 0.f), 1.f);
        }
    }

    // per-output remaining terms
    int gi0 = (b * HH + gy) * WW + gx0;
    float4 gtv = *(const float4*)(gt + gi0);
    float4 cfv = *(const float4*)(conf + gi0);
    float4 ocv = *(const float4*)(occ + gi0);
    float gtA[4] = {gtv.x, gtv.y, gtv.z, gtv.w};
    float cfA[4] = {cfv.x, cfv.y, cfv.z, cfv.w};
    float ocA[4] = {ocv.x, ocv.y, ocv.z, ocv.w};
    int hid0 = (b * H2 + (gy >> 1)) * W2 + (gx0 >> 1);
    float ncP[2] = {g_nc[hid0], g_nc[hid0 + 1]};
    float ndP[2] = {g_nd[hid0], g_nd[hid0 + 1]};

    float s_gtn = 0.f, s_trust = 0.f, s_perr = 0.f, s_valid = 0.f;
    float s_sign = 0.f, s_mag = 0.f, s_act = 0.f, s_sx = 0.f, s_sy = 0.f;
#pragma unroll
    for (int j = 0; j < 4; j++) {
        int gx = gx0 + j;
        float dcen = dS[ty + 1][lx0 + j + 1];
        float xs = (float)gx - dcen;
        float valid = (xs > 0.f && xs < (float)(WW - 1)) ? 1.f : 0.f;
        float perr = (0.85f * (ssAcc[j] * (1.f / 3.f)) + 0.15f * (l1Acc[j] * (1.f / 3.f))) * valid;
        s_perr += perr; s_valid += valid;

        float g = gtA[j];
        float trust = (g > 2.f) ? cfA[j] * ocA[j] : 0.f;
        s_gtn += trust * fabsf(dcen - g);
        s_trust += trust;

        if (gx < WW - 1) {
            float ddx = fabsf(dS[ty + 1][lx0 + j + 2] - dcen);
            s_sx += ddx * __expf(-sidx[j] * (1.f / 3.f));
        }
        if (gy < HH - 1) {
            float ddy = fabsf(dS[ty + 2][lx0 + j + 1] - dcen);
            s_sy += ddy * __expf(-sidy[j] * (1.f / 3.f));
        }

        float ncv = ncP[j >> 1];
        if (ncv > 0.3f) {
            float ndv = ndP[j >> 1];
            s_act += 1.f;
            float s = (ndv > 0.f) ? 1.f : ((ndv < 0.f) ? -1.f : 0.f);
            s_sign += fmaxf(-dcen * s, 0.f);
            s_mag += ncv * fabsf(dcen - ndv);
        }
    }

    __syncthreads();
    float v;
    v = blockReduceSum(s_gtn, sbuf);   if (tid == 0) atomicAdd(&g_acc[0 * 16], (double)v);
    v = blockReduceSum(s_trust, sbuf); if (tid == 0) atomicAdd(&g_acc[1 * 16], (double)v);
    v = blockReduceSum(s_perr, sbuf);  if (tid == 0) atomicAdd(&g_acc[2 * 16], (double)v);
    v = blockReduceSum(s_valid, sbuf); if (tid == 0) atomicAdd(&g_acc[3 * 16], (double)v);
    v = blockReduceSum(s_sign, sbuf);  if (tid == 0) atomicAdd(&g_acc[4 * 16], (double)v);
    v = blockReduceSum(s_mag, sbuf);   if (tid == 0) atomicAdd(&g_acc[5 * 16], (double)v);
    v = blockReduceSum(s_act, sbuf);   if (tid == 0) atomicAdd(&g_acc[6 * 16], (double)v);
    v = blockReduceSum(s_sx, sbuf);    if (tid == 0) atomicAdd(&g_acc[7 * 16], (double)v);
    v = blockReduceSum(s_sy, sbuf);    if (tid == 0) atomicAdd(&g_acc[8 * 16], (double)v);
}

__global__ void finalize_kernel(float* __restrict__ out) {
    double gtl = g_acc[0 * 16] / fmax(g_acc[1 * 16], 1.0);
    double photo = g_acc[2 * 16] / fmax(g_acc[3 * 16], 1.0);
    double n = fmax(g_acc[6 * 16], 1.0);
    double signmag = 0.3 * (g_acc[4 * 16] / n) + 0.7 * (g_acc[5 * 16] / n);
    double smooth = g_acc[7 * 16] / ((double)BB * HH * (WW - 1)) +
                    g_acc[8 * 16] / ((double)BB * (HH - 1) * WW);
    out[0] = (float)(1.0 * gtl + 1.0 * photo + 0.5 * signmag + 0.1 * smooth);
}

// ---------------- launch ----------------
extern "C" void kernel_launch(void* const* d_in, const int* in_sizes, int n_in,
                              void* d_out, int out_size) {
    const float* pred  = (const float*)d_in[0];
    const float* gt    = (const float*)d_in[1];
    const float* conf  = (const float*)d_in[2];
    const float* occ   = (const float*)d_in[3];
    const float* left  = (const float*)d_in[4];
    const float* right = (const float*)d_in[5];
    float* out = (float*)d_out;

    downsample_kernel<<<(BB * H2 * (W2 / 2) + 255) / 256, 256>>>(left, right);
    ncc_kernel<<<BB * H2, 160>>>();
    dim3 tb(16, 8), tg(WW / 64, HH / 8, BB);
    tile_kernel<<<tg, tb>>>(pred, gt, conf, occ, left, right);
    finalize_kernel<<<1, 1>>>(out);
}

// round 4
// speedup vs baseline: 1.1178x; 1.1178x over previous
#include <cuda_runtime.h>
#include <math.h>

#define BB 4
#define HH 544
#define WW 960
#define H2 272
#define W2 480
#define MD 24
#define TILE_BLOCKS 8160

// ---------------- scratch (no allocations allowed) ----------------
__device__ float g_lg[BB * H2 * W2];
__device__ float g_rg[BB * H2 * W2];
__device__ float g_nd[BB * H2 * W2];
__device__ float g_nc[BB * H2 * W2];
// accumulators padded to one 128B line each to avoid LTS atomic serialization
// idx: 0 gtNum 1 gtDen 2 photoNum 3 photoDen 4 signSum 5 magSum 6 activeSum 7 smx 8 smy
__device__ double g_acc[9 * 16];
__device__ int g_counter;   // zero-initialized; self-resetting

// ---------------- helpers ----------------
__device__ __forceinline__ float blockReduceSum(float v, float* sbuf) {
    int tid = threadIdx.x + threadIdx.y * blockDim.x;
    int lane = tid & 31, wid = tid >> 5;
#pragma unroll
    for (int o = 16; o > 0; o >>= 1) v += __shfl_down_sync(0xffffffffu, v, o);
    if (lane == 0) sbuf[wid] = v;
    __syncthreads();
    int nw = (blockDim.x * blockDim.y + 31) >> 5;
    v = (tid < nw) ? sbuf[tid] : 0.f;
    if (wid == 0) {
#pragma unroll
        for (int o = 16; o > 0; o >>= 1) v += __shfl_down_sync(0xffffffffu, v, o);
    }
    __syncthreads();
    return v;  // valid at tid 0
}

// ---------------- kernels ----------------
// half-res grayscale + accumulator/counter zeroing (block 0)
__global__ void downsample_kernel(const float* __restrict__ left,
                                  const float* __restrict__ right) {
    if (blockIdx.x == 0) {
        if (threadIdx.x < 9 * 16) g_acc[threadIdx.x] = 0.0;
        if (threadIdx.x == 0) g_counter = 0;
    }
    int i = blockIdx.x * blockDim.x + threadIdx.x;
    const int NPAIR = W2 / 2;  // 240
    if (i >= BB * H2 * NPAIR) return;
    int px = i % NPAIR;
    int y = (i / NPAIR) % H2;
    int b = i / (NPAIR * H2);
    float l0 = 0.f, l1 = 0.f, r0 = 0.f, r1 = 0.f;
#pragma unroll
    for (int c = 0; c < 3; c++) {
        int base = ((b * 3 + c) * HH + 2 * y) * WW + 4 * px;
        float4 a0 = *(const float4*)(left + base);
        float4 a1 = *(const float4*)(left + base + WW);
        l0 += (a0.x + a0.y + a1.x + a1.y);
        l1 += (a0.z + a0.w + a1.z + a1.w);
        float4 b0 = *(const float4*)(right + base);
        float4 b1 = *(const float4*)(right + base + WW);
        r0 += (b0.x + b0.y + b1.x + b1.y);
        r1 += (b0.z + b0.w + b1.z + b1.w);
    }
    const float S = 0.25f / 3.0f;
    int o = (b * H2 + y) * W2 + 2 * px;
    *(float2*)(g_lg + o) = make_float2(l0 * S, l1 * S);
    *(float2*)(g_rg + o) = make_float2(r0 * S, r1 * S);
}

// NCC disparity search: one CTA per (b, half-res row), 240 threads x 2 adjacent
// columns each. All hot smem traffic is aligned float2 (coalesced).
__global__ __launch_bounds__(240, 4) void ncc_kernel() {
    __shared__ float rgS[11][528];            // rg rows, zero-padded +/-24 (idx = col+24)
    __shared__ float crp[560], cr2p[560];     // rg column sums (idx = col+40), zero pads
    __shared__ float2 HcrF[528];              // (11-box of cr, of cr2) at u = idx-24
    __shared__ float ccS[6][496];             // per-dj cross column sums (idx = col+5)
    float* clp = &ccS[0][0];                  // setup-only aliases (560 floats each)
    float* cl2p = &ccS[0][0] + 560;
    const float NORM = 1.0f / 121.0f;

    int row = blockIdx.x;
    int b = row / H2;
    int y = row - b * H2;
    int t = threadIdx.x;
    int x0 = 2 * t;
    const float* lgB = g_lg + b * H2 * W2;
    const float* rgB = g_rg + b * H2 * W2;

    float2 lg2[11];
    float2 cr = make_float2(0.f, 0.f), cr2 = make_float2(0.f, 0.f);
    float2 cl = make_float2(0.f, 0.f), cl2 = make_float2(0.f, 0.f);
#pragma unroll
    for (int r = 0; r < 11; r++) {
        int yy = y + r - 5;
        float2 lv = make_float2(0.f, 0.f), rv = make_float2(0.f, 0.f);
        if (yy >= 0 && yy < H2) {
            lv = *(const float2*)(lgB + yy * W2 + x0);
            rv = *(const float2*)(rgB + yy * W2 + x0);
        }
        lg2[r] = lv;
        *(float2*)&rgS[r][x0 + 24] = rv;
        if (t < 12) {
            *(float2*)&rgS[r][2 * t] = make_float2(0.f, 0.f);
            *(float2*)&rgS[r][504 + 2 * t] = make_float2(0.f, 0.f);
        }
        cr.x += rv.x; cr.y += rv.y;
        cr2.x += rv.x * rv.x; cr2.y += rv.y * rv.y;
        cl.x += lv.x; cl.y += lv.y;
        cl2.x += lv.x * lv.x; cl2.y += lv.y * lv.y;
    }
    *(float2*)&crp[x0 + 40] = cr;  *(float2*)&cr2p[x0 + 40] = cr2;
    *(float2*)&clp[x0 + 40] = cl;  *(float2*)&cl2p[x0 + 40] = cl2;
    if (t < 20) {
        float2 z = make_float2(0.f, 0.f);
        *(float2*)&crp[2 * t] = z;  *(float2*)&crp[520 + 2 * t] = z;
        *(float2*)&cr2p[2 * t] = z; *(float2*)&cr2p[520 + 2 * t] = z;
        *(float2*)&clp[2 * t] = z;  *(float2*)&clp[520 + 2 * t] = z;
        *(float2*)&cl2p[2 * t] = z; *(float2*)&cl2p[520 + 2 * t] = z;
    }
    __syncthreads();

    // HcrF[i] = 11-box of cr sums centered at col i-24 : taps crp[i+11 .. i+21]
    for (int i = t; i < 528; i += 240) {
        float s = 0.f, s2 = 0.f;
#pragma unroll
        for (int k = 0; k < 11; k++) { s += crp[i + 11 + k]; s2 += cr2p[i + 11 + k]; }
        HcrF[i] = make_float2(s, s2);
    }

    // left stats (2 cols, sliding)
    float lm[2], ls[2];
    {
        float b0 = clp[x0 + 35];
        float m0 = b0;
#pragma unroll
        for (int k = 1; k < 11; k++) m0 += clp[x0 + 35 + k];
        float m1 = m0 - b0 + clp[x0 + 46];
        float c0 = cl2p[x0 + 35];
        float q0 = c0;
#pragma unroll
        for (int k = 1; k < 11; k++) q0 += cl2p[x0 + 35 + k];
        float q1 = q0 - c0 + cl2p[x0 + 46];
        float mm[2] = {m0, m1}, qq[2] = {q0, q1};
#pragma unroll
        for (int j = 0; j < 2; j++) {
            float m = mm[j] * NORM, q = qq[j] * NORM;
            lm[j] = m;
            ls[j] = sqrtf(fmaxf(q - m * m, 1e-8f));
        }
    }
    __syncthreads();

    // zero ccS pads (cols -5..-1 at idx 0..4, cols 480..484 at idx 485..489)
    if (t < 5) {
#pragma unroll
        for (int dj = 0; dj < 6; dj++) { ccS[dj][t] = 0.f; ccS[dj][485 + t] = 0.f; }
    }

    float bestC[2] = {-1.f, -1.f};
    float bestD[2] = {0.f, 0.f};
    bool inter[2];
#pragma unroll
    for (int j = 0; j < 2; j++) inter[j] = (x0 + j >= 5 && x0 + j < 475);

#define NCC_GROUP(D0, OFF)                                                        \
    {                                                                             \
        const int d0 = (D0);                                                      \
        int ua = x0 + d0 + 24 - (OFF);  /* even-aligned window start */           \
        float cc[2][6];                                                           \
        _Pragma("unroll")                                                         \
        for (int j = 0; j < 2; j++)                                               \
            _Pragma("unroll")                                                     \
            for (int dj = 0; dj < 6; dj++) cc[j][dj] = 0.f;                       \
        _Pragma("unroll")                                                         \
        for (int r = 0; r < 11; r++) {                                            \
            float2 p0 = *(float2*)&rgS[r][ua];                                    \
            float2 p1 = *(float2*)&rgS[r][ua + 2];                                \
            float2 p2 = *(float2*)&rgS[r][ua + 4];                                \
            float2 p3 = *(float2*)&rgS[r][ua + 6];                                \
            float w[8] = {p0.x, p0.y, p1.x, p1.y, p2.x, p2.y, p3.x, p3.y};        \
            float lx = lg2[r].x, ly = lg2[r].y;                                   \
            _Pragma("unroll")                                                     \
            for (int dj = 0; dj < 6; dj++) {                                      \
                cc[0][dj] += lx * w[(OFF) + dj];                                  \
                cc[1][dj] += ly * w[(OFF) + 1 + dj];                              \
            }                                                                     \
        }                                                                         \
        _Pragma("unroll")                                                         \
        for (int dj = 0; dj < 6; dj++) {                                          \
            ccS[dj][x0 + 5] = cc[0][dj];                                          \
            ccS[dj][x0 + 6] = cc[1][dj];                                          \
        }                                                                         \
        __syncthreads();                                                          \
        _Pragma("unroll")                                                         \
        for (int dj = 0; dj < 6; dj++) {                                          \
            int d = d0 + dj;                                                      \
            const float* cs = ccS[dj];                                            \
            float2 q0 = *(const float2*)&cs[x0];                                  \
            float2 q1 = *(const float2*)&cs[x0 + 2];                              \
            float2 q2 = *(const float2*)&cs[x0 + 4];                              \
            float2 q3 = *(const float2*)&cs[x0 + 6];                              \
            float2 q4 = *(const float2*)&cs[x0 + 8];                              \
            float2 q5 = *(const float2*)&cs[x0 + 10];                             \
            float w0 = q0.x + q0.y + q1.x + q1.y + q2.x + q2.y + q3.x + q3.y +    \
                       q4.x + q4.y + q5.x;                                        \
            float w1 = w0 - q0.x + q5.y;                                          \
            int u = x0 + d + 24;                                                  \
            float2 h0 = HcrF[u];                                                  \
            float2 h1 = HcrF[u + 1];                                              \
            _Pragma("unroll")                                                     \
            for (int j = 0; j < 2; j++) {                                         \
                float cw = j ? w1 : w0;                                           \
                float rm121, r2121;                                               \
                if (inter[j]) {                                                   \
                    float2 h = j ? h1 : h0;                                       \
                    rm121 = h.x; r2121 = h.y;                                     \
                } else {                                                          \
                    rm121 = 0.f; r2121 = 0.f;                                     \
                    int xj = x0 + j;                                              \
                    _Pragma("unroll")                                             \
                    for (int k = -5; k <= 5; k++) {                               \
                        int uu = xj + k;                                          \
                        if (uu >= 0 && uu < W2) {                                 \
                            rm121 += crp[uu + d + 40];                            \
                            r2121 += cr2p[uu + d + 40];                           \
                        }                                                         \
                    }                                                             \
                }                                                                 \
                float rm = rm121 * NORM;                                          \
                float rstd = sqrtf(fmaxf(r2121 * NORM - rm * rm, 1e-8f));         \
                float ncc = (cw * NORM - lm[j] * rm) / (ls[j] * rstd + 1e-8f);    \
                if (ncc > bestC[j]) { bestC[j] = ncc; bestD[j] = (float)d; }      \
            }                                                                     \
        }                                                                         \
        __syncthreads();                                                          \
    }

    // d = -24..-1 (even group starts, OFF=0), then d = 1..24 (odd starts, OFF=1)
    for (int g = 0; g < 4; g++) NCC_GROUP(6 * g - 24, 0);
    for (int g = 0; g < 4; g++) NCC_GROUP(6 * g + 1, 1);
#undef NCC_GROUP

    int o = (b * H2 + y) * W2 + x0;
    *(float2*)(g_nd + o) = make_float2(bestD[0] * 2.0f, bestD[1] * 2.0f);
    *(float2*)(g_nc + o) = make_float2(fmaxf(bestC[0], 0.f), fmaxf(bestC[1], 0.f));
}

// ONE fused full-res pass: warp-on-the-fly + SSIM/L1 photometric + GT anchor
// + smoothness + sign/magnitude. 32x8 tiles with 1-px halo in smem.
// Last block folds the finalize step.
__global__ void tile_kernel(const float* __restrict__ pred,
                            const float* __restrict__ gt,
                            const float* __restrict__ conf,
                            const float* __restrict__ occ,
                            const float* __restrict__ left,
                            const float* __restrict__ right,
                            float* __restrict__ out) {
    __shared__ float lS[3][10][34];
    __shared__ float wS[3][10][34];
    __shared__ float dS[10][34];
    __shared__ float sbuf[8];
    __shared__ int lastFlag;
    int b = blockIdx.z;
    int tx0 = blockIdx.x * 32, ty0 = blockIdx.y * 8;
    int tid = threadIdx.y * 32 + threadIdx.x;

    // halo load: compute warped right on the fly
    for (int i = tid; i < 10 * 34; i += 256) {
        int col = i % 34;
        int rrow = i / 34;
        int gx = tx0 + col - 1, gy = ty0 + rrow - 1;
        if (gx >= 0 && gx < WW && gy >= 0 && gy < HH) {
            float disp = pred[(b * HH + gy) * WW + gx];
            dS[rrow][col] = disp;
            float xs = (float)gx - disp;
            float xc = fminf(fmaxf(xs, 0.f), (float)(WW - 1));
            float x0f = floorf(xc);
            float w = xc - x0f;
            int x0i = (int)x0f;
            int x1i = min(x0i + 1, WW - 1);
#pragma unroll
            for (int c = 0; c < 3; c++) {
                const float* R = right + ((b * 3 + c) * HH + gy) * WW;
                wS[c][rrow][col] = R[x0i] * (1.f - w) + R[x1i] * w;
                lS[c][rrow][col] = left[((b * 3 + c) * HH + gy) * WW + gx];
            }
        } else {
            dS[rrow][col] = 0.f;
#pragma unroll
            for (int c = 0; c < 3; c++) { wS[c][rrow][col] = 0.f; lS[c][rrow][col] = 0.f; }
        }
    }
    __syncthreads();

    int tx = threadIdx.x, ty = threadIdx.y;
    int gx = tx0 + tx, gy = ty0 + ty;

    // --- photometric (SSIM 3x3 zero-padded pools + L1) ---
    float ssSum = 0.f, l1Sum = 0.f;
    const float N9 = 1.f / 9.f;
    const float C1 = 1e-4f, C2 = 9e-4f;
#pragma unroll
    for (int c = 0; c < 3; c++) {
        float sx = 0.f, sy = 0.f, sxx = 0.f, syy = 0.f, sxy = 0.f;
#pragma unroll
        for (int dy = 0; dy < 3; dy++)
#pragma unroll
            for (int dx = 0; dx < 3; dx++) {
                float xv = lS[c][ty + dy][tx + dx];
                float yv = wS[c][ty + dy][tx + dx];
                sx += xv; sy += yv;
                sxx += xv * xv; syy += yv * yv; sxy += xv * yv;
            }
        float mx = sx * N9, my = sy * N9;
        float vx = fmaxf(sxx * N9 - mx * mx, 0.f);
        float vy = fmaxf(syy * N9 - my * my, 0.f);
        float cxy = sxy * N9 - mx * my;
        float nn = (2.f * mx * my + C1) * (2.f * cxy + C2);
        float dd = (mx * mx + my * my + C1) * (vx + vy + C2);
        float ss = fminf(fmaxf((1.f - nn / dd) * 0.5f, 0.f), 1.f);
        ssSum += ss;
        l1Sum += fabsf(lS[c][ty + 1][tx + 1] - wS[c][ty + 1][tx + 1]);
    }
    float dcen = dS[ty + 1][tx + 1];
    float xs = (float)gx - dcen;
    float valid = (xs > 0.f && xs < (float)(WW - 1)) ? 1.f : 0.f;
    float perr = (0.85f * (ssSum * (1.f / 3.f)) + 0.15f * (l1Sum * (1.f / 3.f))) * valid;

    // --- GT anchor ---
    int gi = (b * HH + gy) * WW + gx;
    float g = gt[gi];
    float trust = (g > 2.f) ? conf[gi] * occ[gi] : 0.f;
    float gtn = trust * fabsf(dcen - g);

    // --- smoothness (uses halo smem) ---
    float a_sx = 0.f, a_sy = 0.f;
    if (gx < WW - 1) {
        float ddx = fabsf(dS[ty + 1][tx + 2] - dcen);
        float idx = (fabsf(lS[0][ty + 1][tx + 2] - lS[0][ty + 1][tx + 1]) +
                     fabsf(lS[1][ty + 1][tx + 2] - lS[1][ty + 1][tx + 1]) +
                     fabsf(lS[2][ty + 1][tx + 2] - lS[2][ty + 1][tx + 1])) * (1.f / 3.f);
        a_sx = ddx * __expf(-idx);
    }
    if (gy < HH - 1) {
        float ddy = fabsf(dS[ty + 2][tx + 1] - dcen);
        float idy = (fabsf(lS[0][ty + 2][tx + 1] - lS[0][ty + 1][tx + 1]) +
                     fabsf(lS[1][ty + 2][tx + 1] - lS[1][ty + 1][tx + 1]) +
                     fabsf(lS[2][ty + 2][tx + 1] - lS[2][ty + 1][tx + 1])) * (1.f / 3.f);
        a_sy = ddy * __expf(-idy);
    }

    // --- sign / magnitude from NCC maps (nearest upsample = index >>1) ---
    float a_sign = 0.f, a_mag = 0.f, a_act = 0.f;
    {
        int hid = (b * H2 + (gy >> 1)) * W2 + (gx >> 1);
        float ncv = g_nc[hid];
        if (ncv > 0.3f) {
            float ndv = g_nd[hid];
            a_act = 1.f;
            float s = (ndv > 0.f) ? 1.f : ((ndv < 0.f) ? -1.f : 0.f);
            a_sign = fmaxf(-dcen * s, 0.f);
            a_mag = ncv * fabsf(dcen - ndv);
        }
    }

    __syncthreads();
    float v;
    v = blockReduceSum(gtn, sbuf);    if (tid == 0) atomicAdd(&g_acc[0 * 16], (double)v);
    v = blockReduceSum(trust, sbuf);  if (tid == 0) atomicAdd(&g_acc[1 * 16], (double)v);
    v = blockReduceSum(perr, sbuf);   if (tid == 0) atomicAdd(&g_acc[2 * 16], (double)v);
    v = blockReduceSum(valid, sbuf);  if (tid == 0) atomicAdd(&g_acc[3 * 16], (double)v);
    v = blockReduceSum(a_sign, sbuf); if (tid == 0) atomicAdd(&g_acc[4 * 16], (double)v);
    v = blockReduceSum(a_mag, sbuf);  if (tid == 0) atomicAdd(&g_acc[5 * 16], (double)v);
    v = blockReduceSum(a_act, sbuf);  if (tid == 0) atomicAdd(&g_acc[6 * 16], (double)v);
    v = blockReduceSum(a_sx, sbuf);   if (tid == 0) atomicAdd(&g_acc[7 * 16], (double)v);
    v = blockReduceSum(a_sy, sbuf);   if (tid == 0) atomicAdd(&g_acc[8 * 16], (double)v);

    // --- finalize (last block) ---
    if (tid == 0) {
        __threadfence();
        int c = atomicAdd(&g_counter, 1);
        lastFlag = (c == TILE_BLOCKS - 1) ? 1 : 0;
    }
    __syncthreads();
    if (lastFlag && tid == 0) {
        __threadfence();
        double gtl = g_acc[0 * 16] / fmax(g_acc[1 * 16], 1.0);
        double photo = g_acc[2 * 16] / fmax(g_acc[3 * 16], 1.0);
        double n = fmax(g_acc[6 * 16], 1.0);
        double signmag = 0.3 * (g_acc[4 * 16] / n) + 0.7 * (g_acc[5 * 16] / n);
        double smooth = g_acc[7 * 16] / ((double)BB * HH * (WW - 1)) +
                        g_acc[8 * 16] / ((double)BB * (HH - 1) * WW);
        out[0] = (float)(1.0 * gtl + 1.0 * photo + 0.5 * signmag + 0.1 * smooth);
        g_counter = 0;
    }
}

// ---------------- launch ----------------
extern "C" void kernel_launch(void* const* d_in, const int* in_sizes, int n_in,
                              void* d_out, int out_size) {
    const float* pred  = (const float*)d_in[0];
    const float* gt    = (const float*)d_in[1];
    const float* conf  = (const float*)d_in[2];
    const float* occ   = (const float*)d_in[3];
    const float* left  = (const float*)d_in[4];
    const float* right = (const float*)d_in[5];
    float* out = (float*)d_out;

    downsample_kernel<<<(BB * H2 * (W2 / 2) + 255) / 256, 256>>>(left, right);
    ncc_kernel<<<BB * H2, 240>>>();
    dim3 tb(32, 8), tg(WW / 32, HH / 8, BB);
    tile_kernel<<<tg, tb>>>(pred, gt, conf, occ, left, right, out);
}

// round 5
// speedup vs baseline: 1.1884x; 1.0631x over previous
#include <cuda_runtime.h>
#include <math.h>

#define BB 4
#define HH 544
#define WW 960
#define H2 272
#define W2 480
#define MD 24
#define TILE_BLOCKS 8160

// ---------------- scratch (no allocations allowed) ----------------
__device__ float g_lg[BB * H2 * W2];
__device__ float g_rg[BB * H2 * W2];
__device__ float g_nd[BB * H2 * W2];
__device__ float g_nc[BB * H2 * W2];
// accumulators padded to one 128B line each to avoid LTS atomic serialization
// idx: 0 gtNum 1 gtDen 2 photoNum 3 photoDen 4 signSum 5 magSum 6 activeSum 7 smx 8 smy
__device__ double g_acc[9 * 16];
__device__ int g_counter;   // zero-initialized; self-resetting

// ---------------- helpers ----------------
__device__ __forceinline__ float blockReduceSum(float v, float* sbuf) {
    int tid = threadIdx.x + threadIdx.y * blockDim.x;
    int lane = tid & 31, wid = tid >> 5;
#pragma unroll
    for (int o = 16; o > 0; o >>= 1) v += __shfl_down_sync(0xffffffffu, v, o);
    if (lane == 0) sbuf[wid] = v;
    __syncthreads();
    int nw = (blockDim.x * blockDim.y + 31) >> 5;
    v = (tid < nw) ? sbuf[tid] : 0.f;
    if (wid == 0) {
#pragma unroll
        for (int o = 16; o > 0; o >>= 1) v += __shfl_down_sync(0xffffffffu, v, o);
    }
    __syncthreads();
    return v;  // valid at tid 0
}

// ---------------- kernels ----------------
// half-res grayscale + accumulator/counter zeroing (block 0)
__global__ void downsample_kernel(const float* __restrict__ left,
                                  const float* __restrict__ right) {
    if (blockIdx.x == 0) {
        if (threadIdx.x < 9 * 16) g_acc[threadIdx.x] = 0.0;
        if (threadIdx.x == 0) g_counter = 0;
    }
    int i = blockIdx.x * blockDim.x + threadIdx.x;
    const int NPAIR = W2 / 2;  // 240
    if (i >= BB * H2 * NPAIR) return;
    int px = i % NPAIR;
    int y = (i / NPAIR) % H2;
    int b = i / (NPAIR * H2);
    float l0 = 0.f, l1 = 0.f, r0 = 0.f, r1 = 0.f;
#pragma unroll
    for (int c = 0; c < 3; c++) {
        int base = ((b * 3 + c) * HH + 2 * y) * WW + 4 * px;
        float4 a0 = *(const float4*)(left + base);
        float4 a1 = *(const float4*)(left + base + WW);
        l0 += (a0.x + a0.y + a1.x + a1.y);
        l1 += (a0.z + a0.w + a1.z + a1.w);
        float4 b0 = *(const float4*)(right + base);
        float4 b1 = *(const float4*)(right + base + WW);
        r0 += (b0.x + b0.y + b1.x + b1.y);
        r1 += (b0.z + b0.w + b1.z + b1.w);
    }
    const float S = 0.25f / 3.0f;
    int o = (b * H2 + y) * W2 + 2 * px;
    *(float2*)(g_lg + o) = make_float2(l0 * S, l1 * S);
    *(float2*)(g_rg + o) = make_float2(r0 * S, r1 * S);
}

// NCC disparity search: one CTA per (b, half-res row), 480 threads (one per column).
// Round-2 proven dataflow; __launch_bounds__(480,2) for 2 CTAs/SM co-residency.
// Disparities in groups of 6 -> 2 syncs per group (16 total).
__global__ void __launch_bounds__(480, 2) ncc_kernel() {
    __shared__ float rgS[11][528];                       // rg rows, zero-padded +/-24
    __shared__ float crp[560], cr2p[560];                // rg column sums, padded +/-40
    __shared__ float clp[560], cl2p[560];                // lg column sums, padded +/-40
    __shared__ float HcrS[528], Hcr2S[528];              // 11-box of crp at u in [-24,503]
    __shared__ float ccS[6][496];                        // cross column sums per group, padded +/-8
    const float NORM = 1.0f / 121.0f;

    int row = blockIdx.x;
    int b = row / H2;
    int y = row - b * H2;
    int x = threadIdx.x;
    const float* lgB = g_lg + b * H2 * W2;
    const float* rgB = g_rg + b * H2 * W2;

    float lgR[11];
    float cr = 0.f, cr2 = 0.f, cl = 0.f, cl2 = 0.f;
#pragma unroll
    for (int r = 0; r < 11; r++) {
        int yy = y + r - 5;
        float lv = 0.f, rv = 0.f;
        if (yy >= 0 && yy < H2) {
            lv = lgB[yy * W2 + x];
            rv = rgB[yy * W2 + x];
        }
        lgR[r] = lv;
        rgS[r][x + 24] = rv;
        if (x < 24) { rgS[r][x] = 0.f; rgS[r][x + 504] = 0.f; }
        cr += rv; cr2 += rv * rv;
        cl += lv; cl2 += lv * lv;
    }
    crp[x + 40] = cr;  cr2p[x + 40] = cr2;
    clp[x + 40] = cl;  cl2p[x + 40] = cl2;
    if (x < 40)  { crp[x] = 0.f; cr2p[x] = 0.f; clp[x] = 0.f; cl2p[x] = 0.f; }
    if (x >= 440){ crp[x + 80] = 0.f; cr2p[x + 80] = 0.f; clp[x + 80] = 0.f; cl2p[x + 80] = 0.f; }
    if (x < 8) {
#pragma unroll
        for (int j = 0; j < 6; j++) { ccS[j][x] = 0.f; ccS[j][488 + x] = 0.f; }
    }
    __syncthreads();

    // horizontal 11-box of the rg column sums: Hcr(u)=sum_{k=-5..5} crp[u+k], u = x-24 (+ tail)
    {
        float s = 0.f, s2 = 0.f;
#pragma unroll
        for (int k = -5; k <= 5; k++) { s += crp[x + 16 + k]; s2 += cr2p[x + 16 + k]; }
        HcrS[x] = s; Hcr2S[x] = s2;
        if (x < 48) {
            float t = 0.f, t2 = 0.f;
#pragma unroll
            for (int k = -5; k <= 5; k++) { t += crp[x + 496 + k]; t2 += cr2p[x + 496 + k]; }
            HcrS[x + 480] = t; Hcr2S[x + 480] = t2;
        }
    }
    // left stats lm, ls
    float lm = 0.f, lq = 0.f;
#pragma unroll
    for (int k = -5; k <= 5; k++) { lm += clp[x + 40 + k]; lq += cl2p[x + 40 + k]; }
    lm *= NORM; lq *= NORM;
    float ls = sqrtf(fmaxf(lq - lm * lm, 1e-8f));
    __syncthreads();

    float bestC = -1.0f, bestD = 0.0f;
    bool interior = (x >= 5 && x < 475);
    for (int g = 0; g < 8; g++) {
        float cc[6];
#pragma unroll
        for (int j = 0; j < 6; j++) {
            int idx = g * 6 + j;
            int d = (idx < 24) ? (idx - 24) : (idx - 23);
            float s = 0.f;
#pragma unroll
            for (int r = 0; r < 11; r++) s += lgR[r] * rgS[r][x + d + 24];
            cc[j] = s;
        }
#pragma unroll
        for (int j = 0; j < 6; j++) ccS[j][x + 8] = cc[j];
        __syncthreads();
#pragma unroll
        for (int j = 0; j < 6; j++) {
            int idx = g * 6 + j;
            int d = (idx < 24) ? (idx - 24) : (idx - 23);
            // own column (k=0) kept in register: 10 smem taps instead of 11
            float cross121 = cc[j];
#pragma unroll
            for (int k = -5; k < 0; k++) cross121 += ccS[j][x + 8 + k];
#pragma unroll
            for (int k = 1; k <= 5; k++) cross121 += ccS[j][x + 8 + k];
            float rm121, r2121;
            if (interior) {
                rm121 = HcrS[x + d + 24];
                r2121 = Hcr2S[x + d + 24];
            } else {
                rm121 = 0.f; r2121 = 0.f;
#pragma unroll
                for (int k = -5; k <= 5; k++) {
                    int u = x + k;
                    if (u >= 0 && u < W2) {
                        rm121 += crp[u + d + 40];
                        r2121 += cr2p[u + d + 40];
                    }
                }
            }
            float rm = rm121 * NORM;
            float rstd = sqrtf(fmaxf(r2121 * NORM - rm * rm, 1e-8f));
            float ncc = (cross121 * NORM - lm * rm) / (ls * rstd + 1e-8f);
            if (ncc > bestC) { bestC = ncc; bestD = (float)d; }
        }
        __syncthreads();
    }
    int o = (b * H2 + y) * W2 + x;
    g_nd[o] = bestD * 2.0f;
    g_nc[o] = fmaxf(bestC, 0.f);
}

// ONE fused full-res pass: warp-on-the-fly + SSIM/L1 photometric + GT anchor
// + smoothness + sign/magnitude. 32x8 tiles with 1-px halo in smem.
// Last block folds the finalize step.
__global__ void tile_kernel(const float* __restrict__ pred,
                            const float* __restrict__ gt,
                            const float* __restrict__ conf,
                            const float* __restrict__ occ,
                            const float* __restrict__ left,
                            const float* __restrict__ right,
                            float* __restrict__ out) {
    __shared__ float lS[3][10][34];
    __shared__ float wS[3][10][34];
    __shared__ float dS[10][34];
    __shared__ float sbuf[8];
    __shared__ int lastFlag;
    int b = blockIdx.z;
    int tx0 = blockIdx.x * 32, ty0 = blockIdx.y * 8;
    int tid = threadIdx.y * 32 + threadIdx.x;

    // halo load: compute warped right on the fly
    for (int i = tid; i < 10 * 34; i += 256) {
        int col = i % 34;
        int rrow = i / 34;
        int gx = tx0 + col - 1, gy = ty0 + rrow - 1;
        if (gx >= 0 && gx < WW && gy >= 0 && gy < HH) {
            float disp = pred[(b * HH + gy) * WW + gx];
            dS[rrow][col] = disp;
            float xs = (float)gx - disp;
            float xc = fminf(fmaxf(xs, 0.f), (float)(WW - 1));
            float x0f = floorf(xc);
            float w = xc - x0f;
            int x0i = (int)x0f;
            int x1i = min(x0i + 1, WW - 1);
#pragma unroll
            for (int c = 0; c < 3; c++) {
                const float* R = right + ((b * 3 + c) * HH + gy) * WW;
                wS[c][rrow][col] = R[x0i] * (1.f - w) + R[x1i] * w;
                lS[c][rrow][col] = left[((b * 3 + c) * HH + gy) * WW + gx];
            }
        } else {
            dS[rrow][col] = 0.f;
#pragma unroll
            for (int c = 0; c < 3; c++) { wS[c][rrow][col] = 0.f; lS[c][rrow][col] = 0.f; }
        }
    }
    __syncthreads();

    int tx = threadIdx.x, ty = threadIdx.y;
    int gx = tx0 + tx, gy = ty0 + ty;

    // --- photometric (SSIM 3x3 zero-padded pools + L1) ---
    float ssSum = 0.f, l1Sum = 0.f;
    const float N9 = 1.f / 9.f;
    const float C1 = 1e-4f, C2 = 9e-4f;
#pragma unroll
    for (int c = 0; c < 3; c++) {
        float sx = 0.f, sy = 0.f, sxx = 0.f, syy = 0.f, sxy = 0.f;
#pragma unroll
        for (int dy = 0; dy < 3; dy++)
#pragma unroll
            for (int dx = 0; dx < 3; dx++) {
                float xv = lS[c][ty + dy][tx + dx];
                float yv = wS[c][ty + dy][tx + dx];
                sx += xv; sy += yv;
                sxx += xv * xv; syy += yv * yv; sxy += xv * yv;
            }
        float mx = sx * N9, my = sy * N9;
        float vx = fmaxf(sxx * N9 - mx * mx, 0.f);
        float vy = fmaxf(syy * N9 - my * my, 0.f);
        float cxy = sxy * N9 - mx * my;
        float nn = (2.f * mx * my + C1) * (2.f * cxy + C2);
        float dd = (mx * mx + my * my + C1) * (vx + vy + C2);
        float ss = fminf(fmaxf((1.f - nn / dd) * 0.5f, 0.f), 1.f);
        ssSum += ss;
        l1Sum += fabsf(lS[c][ty + 1][tx + 1] - wS[c][ty + 1][tx + 1]);
    }
    float dcen = dS[ty + 1][tx + 1];
    float xs = (float)gx - dcen;
    float valid = (xs > 0.f && xs < (float)(WW - 1)) ? 1.f : 0.f;
    float perr = (0.85f * (ssSum * (1.f / 3.f)) + 0.15f * (l1Sum * (1.f / 3.f))) * valid;

    // --- GT anchor ---
    int gi = (b * HH + gy) * WW + gx;
    float g = gt[gi];
    float trust = (g > 2.f) ? conf[gi] * occ[gi] : 0.f;
    float gtn = trust * fabsf(dcen - g);

    // --- smoothness (uses halo smem) ---
    float a_sx = 0.f, a_sy = 0.f;
    if (gx < WW - 1) {
        float ddx = fabsf(dS[ty + 1][tx + 2] - dcen);
        float idx = (fabsf(lS[0][ty + 1][tx + 2] - lS[0][ty + 1][tx + 1]) +
                     fabsf(lS[1][ty + 1][tx + 2] - lS[1][ty + 1][tx + 1]) +
                     fabsf(lS[2][ty + 1][tx + 2] - lS[2][ty + 1][tx + 1])) * (1.f / 3.f);
        a_sx = ddx * __expf(-idx);
    }
    if (gy < HH - 1) {
        float ddy = fabsf(dS[ty + 2][tx + 1] - dcen);
        float idy = (fabsf(lS[0][ty + 2][tx + 1] - lS[0][ty + 1][tx + 1]) +
                     fabsf(lS[1][ty + 2][tx + 1] - lS[1][ty + 1][tx + 1]) +
                     fabsf(lS[2][ty + 2][tx + 1] - lS[2][ty + 1][tx + 1])) * (1.f / 3.f);
        a_sy = ddy * __expf(-idy);
    }

    // --- sign / magnitude from NCC maps (nearest upsample = index >>1) ---
    float a_sign = 0.f, a_mag = 0.f, a_act = 0.f;
    {
        int hid = (b * H2 + (gy >> 1)) * W2 + (gx >> 1);
        float ncv = g_nc[hid];
        if (ncv > 0.3f) {
            float ndv = g_nd[hid];
            a_act = 1.f;
            float s = (ndv > 0.f) ? 1.f : ((ndv < 0.f) ? -1.f : 0.f);
            a_sign = fmaxf(-dcen * s, 0.f);
            a_mag = ncv * fabsf(dcen - ndv);
        }
    }

    __syncthreads();
    float v;
    v = blockReduceSum(gtn, sbuf);    if (tid == 0) atomicAdd(&g_acc[0 * 16], (double)v);
    v = blockReduceSum(trust, sbuf);  if (tid == 0) atomicAdd(&g_acc[1 * 16], (double)v);
    v = blockReduceSum(perr, sbuf);   if (tid == 0) atomicAdd(&g_acc[2 * 16], (double)v);
    v = blockReduceSum(valid, sbuf);  if (tid == 0) atomicAdd(&g_acc[3 * 16], (double)v);
    v = blockReduceSum(a_sign, sbuf); if (tid == 0) atomicAdd(&g_acc[4 * 16], (double)v);
    v = blockReduceSum(a_mag, sbuf);  if (tid == 0) atomicAdd(&g_acc[5 * 16], (double)v);
    v = blockReduceSum(a_act, sbuf);  if (tid == 0) atomicAdd(&g_acc[6 * 16], (double)v);
    v = blockReduceSum(a_sx, sbuf);   if (tid == 0) atomicAdd(&g_acc[7 * 16], (double)v);
    v = blockReduceSum(a_sy, sbuf);   if (tid == 0) atomicAdd(&g_acc[8 * 16], (double)v);

    // --- finalize (last block) ---
    if (tid == 0) {
        __threadfence();
        int c = atomicAdd(&g_counter, 1);
        lastFlag = (c == TILE_BLOCKS - 1) ? 1 : 0;
    }
    __syncthreads();
    if (lastFlag && tid == 0) {
        __threadfence();
        double gtl = g_acc[0 * 16] / fmax(g_acc[1 * 16], 1.0);
        double photo = g_acc[2 * 16] / fmax(g_acc[3 * 16], 1.0);
        double n = fmax(g_acc[6 * 16], 1.0);
        double signmag = 0.3 * (g_acc[4 * 16] / n) + 0.7 * (g_acc[5 * 16] / n);
        double smooth = g_acc[7 * 16] / ((double)BB * HH * (WW - 1)) +
                        g_acc[8 * 16] / ((double)BB * (HH - 1) * WW);
        out[0] = (float)(1.0 * gtl + 1.0 * photo + 0.5 * signmag + 0.1 * smooth);
        g_counter = 0;
    }
}

// ---------------- launch ----------------
extern "C" void kernel_launch(void* const* d_in, const int* in_sizes, int n_in,
                              void* d_out, int out_size) {
    const float* pred  = (const float*)d_in[0];
    const float* gt    = (const float*)d_in[1];
    const float* conf  = (const float*)d_in[2];
    const float* occ   = (const float*)d_in[3];
    const float* left  = (const float*)d_in[4];
    const float* right = (const float*)d_in[5];
    float* out = (float*)d_out;

    downsample_kernel<<<(BB * H2 * (W2 / 2) + 255) / 256, 256>>>(left, right);
    ncc_kernel<<<BB * H2, 480>>>();
    dim3 tb(32, 8), tg(WW / 32, HH / 8, BB);
    tile_kernel<<<tg, tb>>>(pred, gt, conf, occ, left, right, out);
}

// round 7
// speedup vs baseline: 1.2670x; 1.0661x over previous
#include <cuda_runtime.h>
#include <math.h>

#define BB 4
#define HH 544
#define WW 960
#define H2 272
#define W2 480
#define MD 24
#define TILE_BLOCKS 4080

// ---------------- scratch (no allocations allowed) ----------------
__device__ float g_lg[BB * H2 * W2];
__device__ float g_rg[BB * H2 * W2];
__device__ float g_nd[BB * H2 * W2];
__device__ float g_nc[BB * H2 * W2];
// accumulators padded to one 128B line each to avoid LTS atomic serialization
// idx: 0 gtNum 1 gtDen 2 photoNum 3 photoDen 4 signSum 5 magSum 6 activeSum 7 smx 8 smy
__device__ double g_acc[9 * 16];
__device__ int g_counter;   // zero-initialized; self-resetting

// ---------------- helpers ----------------
__device__ __forceinline__ float blockReduceSum(float v, float* sbuf) {
    int tid = threadIdx.x + threadIdx.y * blockDim.x;
    int lane = tid & 31, wid = tid >> 5;
#pragma unroll
    for (int o = 16; o > 0; o >>= 1) v += __shfl_down_sync(0xffffffffu, v, o);
    if (lane == 0) sbuf[wid] = v;
    __syncthreads();
    int nw = (blockDim.x * blockDim.y + 31) >> 5;
    v = (tid < nw) ? sbuf[tid] : 0.f;
    if (wid == 0) {
#pragma unroll
        for (int o = 16; o > 0; o >>= 1) v += __shfl_down_sync(0xffffffffu, v, o);
    }
    __syncthreads();
    return v;  // valid at tid 0
}

// ---------------- kernels ----------------
// half-res grayscale + accumulator/counter zeroing (block 0)
__global__ void downsample_kernel(const float* __restrict__ left,
                                  const float* __restrict__ right) {
    if (blockIdx.x == 0) {
        if (threadIdx.x < 9 * 16) g_acc[threadIdx.x] = 0.0;
        if (threadIdx.x == 0) g_counter = 0;
    }
    int i = blockIdx.x * blockDim.x + threadIdx.x;
    const int NPAIR = W2 / 2;  // 240
    if (i >= BB * H2 * NPAIR) return;
    int px = i % NPAIR;
    int y = (i / NPAIR) % H2;
    int b = i / (NPAIR * H2);
    float l0 = 0.f, l1 = 0.f, r0 = 0.f, r1 = 0.f;
#pragma unroll
    for (int c = 0; c < 3; c++) {
        int base = ((b * 3 + c) * HH + 2 * y) * WW + 4 * px;
        float4 a0 = *(const float4*)(left + base);
        float4 a1 = *(const float4*)(left + base + WW);
        l0 += (a0.x + a0.y + a1.x + a1.y);
        l1 += (a0.z + a0.w + a1.z + a1.w);
        float4 b0 = *(const float4*)(right + base);
        float4 b1 = *(const float4*)(right + base + WW);
        r0 += (b0.x + b0.y + b1.x + b1.y);
        r1 += (b0.z + b0.w + b1.z + b1.w);
    }
    const float S = 0.25f / 3.0f;
    int o = (b * H2 + y) * W2 + 2 * px;
    *(float2*)(g_lg + o) = make_float2(l0 * S, l1 * S);
    *(float2*)(g_rg + o) = make_float2(r0 * S, r1 * S);
}

// NCC disparity search: one CTA per (b, PAIR of half-res rows), 480 threads
// (one per column). Row y0+1 stats derived from row y0 by register rolling:
// cc1 = cc0 - lg[0]*rg[0] + lg[11]*rg[11] (2 LDS instead of 11).
__global__ void __launch_bounds__(480, 2) ncc_kernel() {
    __shared__ float rgS[12][528];                        // rows y0-5..y0+6, zero-padded +/-24
    __shared__ float crp0[560], cr2p0[560];               // rg column sums row0 window (idx=x+40)
    __shared__ float crp1[560], cr2p1[560];               // rg column sums row1 window
    __shared__ float Hcr0[528], Hcr20[528];               // 11-box of crp0 at u=idx-24
    __shared__ float Hcr1[528], Hcr21[528];               // 11-box of crp1
    __shared__ float ccS[2][6][496];                      // cross column sums, idx = x+8
    float* clp0 = &ccS[0][0][0];                          // setup-only aliases (560 each)
    float* cl2p0 = clp0 + 560;
    float* clp1 = clp0 + 1120;
    float* cl2p1 = clp0 + 1680;
    const float NORM = 1.0f / 121.0f;

    int pr = blockIdx.x;
    int b = pr / (H2 / 2);
    int yp = pr - b * (H2 / 2);
    int y0 = 2 * yp;
    int x = threadIdx.x;
    const float* lgB = g_lg + b * H2 * W2;
    const float* rgB = g_rg + b * H2 * W2;

    float lgR[12];
    float cr0 = 0.f, cr20 = 0.f, cl0 = 0.f, cl20 = 0.f;
    float rv0 = 0.f, rv11 = 0.f;
#pragma unroll
    for (int r = 0; r < 12; r++) {
        int yy = y0 + r - 5;
        float lv = 0.f, rv = 0.f;
        if (yy >= 0 && yy < H2) { lv = lgB[yy * W2 + x]; rv = rgB[yy * W2 + x]; }
        lgR[r] = lv;
        rgS[r][x + 24] = rv;
        if (x < 24) { rgS[r][x] = 0.f; rgS[r][x + 504] = 0.f; }
        if (r < 11) { cr0 += rv; cr20 += rv * rv; cl0 += lv; cl20 += lv * lv; }
        if (r == 0) rv0 = rv;
        if (r == 11) rv11 = rv;
    }
    float cr1 = cr0 - rv0 + rv11;
    float cr21 = cr20 - rv0 * rv0 + rv11 * rv11;
    float cl1 = cl0 - lgR[0] + lgR[11];
    float cl21 = cl20 - lgR[0] * lgR[0] + lgR[11] * lgR[11];

    crp0[x + 40] = cr0; cr2p0[x + 40] = cr20;
    crp1[x + 40] = cr1; cr2p1[x + 40] = cr21;
    clp0[x + 40] = cl0; cl2p0[x + 40] = cl20;
    clp1[x + 40] = cl1; cl2p1[x + 40] = cl21;
    if (x < 40) {
        crp0[x] = 0.f; cr2p0[x] = 0.f; crp1[x] = 0.f; cr2p1[x] = 0.f;
        clp0[x] = 0.f; cl2p0[x] = 0.f; clp1[x] = 0.f; cl2p1[x] = 0.f;
    }
    if (x >= 440) {
        crp0[x + 80] = 0.f; cr2p0[x + 80] = 0.f; crp1[x + 80] = 0.f; cr2p1[x + 80] = 0.f;
        clp0[x + 80] = 0.f; cl2p0[x + 80] = 0.f; clp1[x + 80] = 0.f; cl2p1[x + 80] = 0.f;
    }
    __syncthreads();

    // Hcr[i] = 11-box of cr centered at col i-24 : taps crp[i+11..i+21]
    for (int i = x; i < 528; i += 480) {
        float s0 = 0.f, s20 = 0.f, s1 = 0.f, s21 = 0.f;
#pragma unroll
        for (int k = 0; k < 11; k++) {
            s0 += crp0[i + 11 + k]; s20 += cr2p0[i + 11 + k];
            s1 += crp1[i + 11 + k]; s21 += cr2p1[i + 11 + k];
        }
        Hcr0[i] = s0; Hcr20[i] = s20; Hcr1[i] = s1; Hcr21[i] = s21;
    }
    // left stats for both rows
    float lm0 = 0.f, lq0 = 0.f, lm1 = 0.f, lq1 = 0.f;
#pragma unroll
    for (int k = 0; k < 11; k++) {
        lm0 += clp0[x + 35 + k]; lq0 += cl2p0[x + 35 + k];
        lm1 += clp1[x + 35 + k]; lq1 += cl2p1[x + 35 + k];
    }
    lm0 *= NORM; lq0 *= NORM; lm1 *= NORM; lq1 *= NORM;
    float ls0 = sqrtf(fmaxf(lq0 - lm0 * lm0, 1e-8f));
    float ls1 = sqrtf(fmaxf(lq1 - lm1 * lm1, 1e-8f));
    __syncthreads();   // clp reads done; ccS region now free

    // zero ccS pads (idx 0..7, 488..495) — disjoint from data writes below
    if (x < 8) {
#pragma unroll
        for (int rr = 0; rr < 2; rr++)
#pragma unroll
            for (int j = 0; j < 6; j++) { ccS[rr][j][x] = 0.f; ccS[rr][j][488 + x] = 0.f; }
    }

    float bestC0 = -1.f, bestD0 = 0.f, bestC1 = -1.f, bestD1 = 0.f;
    bool interior = (x >= 5 && x < 475);
    for (int g = 0; g < 8; g++) {
        float cc0r[6], cc1r[6];
#pragma unroll
        for (int j = 0; j < 6; j++) {
            int idx = g * 6 + j;
            int d = (idx < 24) ? (idx - 24) : (idx - 23);
            int u = x + d + 24;
            float w0v = rgS[0][u];
            float s = lgR[0] * w0v;
#pragma unroll
            for (int r = 1; r < 11; r++) s += lgR[r] * rgS[r][u];
            cc0r[j] = s;
            float w11v = rgS[11][u];
            cc1r[j] = s - lgR[0] * w0v + lgR[11] * w11v;
            ccS[0][j][x + 8] = s;
            ccS[1][j][x + 8] = cc1r[j];
        }
        __syncthreads();
#pragma unroll
        for (int j = 0; j < 6; j++) {
            int idx = g * 6 + j;
            int d = (idx < 24) ? (idx - 24) : (idx - 23);
            // cross boxes: own column kept in register (10 taps each)
            float cross0 = cc0r[j], cross1 = cc1r[j];
#pragma unroll
            for (int k = -5; k < 0; k++) { cross0 += ccS[0][j][x + 8 + k]; cross1 += ccS[1][j][x + 8 + k]; }
#pragma unroll
            for (int k = 1; k <= 5; k++) { cross0 += ccS[0][j][x + 8 + k]; cross1 += ccS[1][j][x + 8 + k]; }
            float rm0_, r20_, rm1_, r21_;
            if (interior) {
                int u = x + d + 24;
                rm0_ = Hcr0[u]; r20_ = Hcr20[u]; rm1_ = Hcr1[u]; r21_ = Hcr21[u];
            } else {
                rm0_ = 0.f; r20_ = 0.f; rm1_ = 0.f; r21_ = 0.f;
#pragma unroll
                for (int k = -5; k <= 5; k++) {
                    int uu = x + k;
                    if (uu >= 0 && uu < W2) {
                        rm0_ += crp0[uu + d + 40]; r20_ += cr2p0[uu + d + 40];
                        rm1_ += crp1[uu + d + 40]; r21_ += cr2p1[uu + d + 40];
                    }
                }
            }
            float rm = rm0_ * NORM;
            float rstd = sqrtf(fmaxf(r20_ * NORM - rm * rm, 1e-8f));
            float ncc = (cross0 * NORM - lm0 * rm) / (ls0 * rstd + 1e-8f);
            if (ncc > bestC0) { bestC0 = ncc; bestD0 = (float)d; }
            rm = rm1_ * NORM;
            rstd = sqrtf(fmaxf(r21_ * NORM - rm * rm, 1e-8f));
            ncc = (cross1 * NORM - lm1 * rm) / (ls1 * rstd + 1e-8f);
            if (ncc > bestC1) { bestC1 = ncc; bestD1 = (float)d; }
        }
        __syncthreads();
    }
    int o = (b * H2 + y0) * W2 + x;
    g_nd[o] = bestD0 * 2.0f;
    g_nc[o] = fmaxf(bestC0, 0.f);
    g_nd[o + W2] = bestD1 * 2.0f;
    g_nc[o + W2] = fmaxf(bestC1, 0.f);
}

// ONE fused full-res pass: warp-on-the-fly + SSIM/L1 photometric + GT anchor
// + smoothness + sign/magnitude. 64x8 tiles, 128 threads, 4 outputs/thread.
// Last block folds the finalize step.
__global__ __launch_bounds__(128) void tile_kernel(const float* __restrict__ pred,
                                                   const float* __restrict__ gt,
                                                   const float* __restrict__ conf,
                                                   const float* __restrict__ occ,
                                                   const float* __restrict__ left,
                                                   const float* __restrict__ right,
                                                   float* __restrict__ out) {
    __shared__ float lS[3][10][66];
    __shared__ float wS[3][10][66];
    __shared__ float dS[10][66];
    __shared__ float sbuf[8];
    __shared__ int lastFlag;
    int b = blockIdx.z;
    int tx0 = blockIdx.x * 64, ty0 = blockIdx.y * 8;
    int tid = threadIdx.y * 16 + threadIdx.x;

    // halo load: compute warped right on the fly
    for (int i = tid; i < 10 * 66; i += 128) {
        int col = i % 66;
        int rrow = i / 66;
        int gx = tx0 + col - 1, gy = ty0 + rrow - 1;
        if (gx >= 0 && gx < WW && gy >= 0 && gy < HH) {
            float disp = pred[(b * HH + gy) * WW + gx];
            dS[rrow][col] = disp;
            float xs = (float)gx - disp;
            float xc = fminf(fmaxf(xs, 0.f), (float)(WW - 1));
            float x0f = floorf(xc);
            float w = xc - x0f;
            int x0i = (int)x0f;
            int x1i = min(x0i + 1, WW - 1);
#pragma unroll
            for (int c = 0; c < 3; c++) {
                const float* R = right + ((b * 3 + c) * HH + gy) * WW;
                wS[c][rrow][col] = R[x0i] * (1.f - w) + R[x1i] * w;
                lS[c][rrow][col] = left[((b * 3 + c) * HH + gy) * WW + gx];
            }
        } else {
            dS[rrow][col] = 0.f;
#pragma unroll
            for (int c = 0; c < 3; c++) { wS[c][rrow][col] = 0.f; lS[c][rrow][col] = 0.f; }
        }
    }
    __syncthreads();

    int tx = threadIdx.x, ty = threadIdx.y;
    int lx0 = 4 * tx;                 // local col of first output
    int gx0 = tx0 + lx0, gy = ty0 + ty;

    float ssAcc[4] = {0, 0, 0, 0}, l1Acc[4] = {0, 0, 0, 0};
    float sidx[4] = {0, 0, 0, 0}, sidy[4] = {0, 0, 0, 0};
    const float N9 = 1.f / 9.f;
    const float C1 = 1e-4f, C2 = 9e-4f;
#pragma unroll
    for (int c = 0; c < 3; c++) {
        float win[4][5];
#pragma unroll
        for (int j = 0; j < 4; j++)
#pragma unroll
            for (int q = 0; q < 5; q++) win[j][q] = 0.f;
        float prev1 = 0.f;
#pragma unroll
        for (int u = 0; u < 6; u++) {
            float l0 = lS[c][ty][lx0 + u], l1 = lS[c][ty + 1][lx0 + u], l2 = lS[c][ty + 2][lx0 + u];
            float m0 = wS[c][ty][lx0 + u], m1 = wS[c][ty + 1][lx0 + u], m2 = wS[c][ty + 2][lx0 + u];
            float cA = l0 + l1 + l2;
            float cB = m0 + m1 + m2;
            float cC = l0 * l0 + l1 * l1 + l2 * l2;
            float cD = m0 * m0 + m1 * m1 + m2 * m2;
            float cE = l0 * m0 + l1 * m1 + l2 * m2;
#pragma unroll
            for (int j = 0; j < 4; j++) {
                if (u >= j && u <= j + 2) {
                    win[j][0] += cA; win[j][1] += cB; win[j][2] += cC;
                    win[j][3] += cD; win[j][4] += cE;
                }
            }
            if (u >= 1 && u <= 4) {
                l1Acc[u - 1] += fabsf(l1 - m1);
                sidy[u - 1] += fabsf(l2 - l1);
            }
            if (u >= 2) sidx[u - 2] += fabsf(l1 - prev1);
            prev1 = l1;
        }
#pragma unroll
        for (int j = 0; j < 4; j++) {
            float mx = win[j][0] * N9, my = win[j][1] * N9;
            float vx = fmaxf(win[j][2] * N9 - mx * mx, 0.f);
            float vy = fmaxf(win[j][3] * N9 - my * my, 0.f);
            float cxy = win[j][4] * N9 - mx * my;
            float nn = (2.f * mx * my + C1) * (2.f * cxy + C2);
            float dd = (mx * mx + my * my + C1) * (vx + vy + C2);
            ssAcc[j] += fminf(fmaxf((1.f - nn / dd) * 0.5f, 0.f), 1.f);
        }
    }

    // per-output remaining terms
    int gi0 = (b * HH + gy) * WW + gx0;
    float4 gtv = *(const float4*)(gt + gi0);
    float4 cfv = *(const float4*)(conf + gi0);
    float4 ocv = *(const float4*)(occ + gi0);
    float gtA[4] = {gtv.x, gtv.y, gtv.z, gtv.w};
    float cfA[4] = {cfv.x, cfv.y, cfv.z, cfv.w};
    float ocA[4] = {ocv.x, ocv.y, ocv.z, ocv.w};
    int hid0 = (b * H2 + (gy >> 1)) * W2 + (gx0 >> 1);
    float ncP[2] = {g_nc[hid0], g_nc[hid0 + 1]};
    float ndP[2] = {g_nd[hid0], g_nd[hid0 + 1]};

    float s_gtn = 0.f, s_trust = 0.f, s_perr = 0.f, s_valid = 0.f;
    float s_sign = 0.f, s_mag = 0.f, s_act = 0.f, s_sx = 0.f, s_sy = 0.f;
#pragma unroll
    for (int j = 0; j < 4; j++) {
        int gx = gx0 + j;
        float dcen = dS[ty + 1][lx0 + j + 1];
        float xs = (float)gx - dcen;
        float valid = (xs > 0.f && xs < (float)(WW - 1)) ? 1.f : 0.f;
        float perr = (0.85f * (ssAcc[j] * (1.f / 3.f)) + 0.15f * (l1Acc[j] * (1.f / 3.f))) * valid;
        s_perr += perr; s_valid += valid;

        float g = gtA[j];
        float trust = (g > 2.f) ? cfA[j] * ocA[j] : 0.f;
        s_gtn += trust * fabsf(dcen - g);
        s_trust += trust;

        if (gx < WW - 1) {
            float ddx = fabsf(dS[ty + 1][lx0 + j + 2] - dcen);
            s_sx += ddx * __expf(-sidx[j] * (1.f / 3.f));
        }
        if (gy < HH - 1) {
            float ddy = fabsf(dS[ty + 2][lx0 + j + 1] - dcen);
            s_sy += ddy * __expf(-sidy[j] * (1.f / 3.f));
        }

        float ncv = ncP[j >> 1];
        if (ncv > 0.3f) {
            float ndv = ndP[j >> 1];
            s_act += 1.f;
            float s = (ndv > 0.f) ? 1.f : ((ndv < 0.f) ? -1.f : 0.f);
            s_sign += fmaxf(-dcen * s, 0.f);
            s_mag += ncv * fabsf(dcen - ndv);
        }
    }

    __syncthreads();
    float v;
    v = blockReduceSum(s_gtn, sbuf);   if (tid == 0) atomicAdd(&g_acc[0 * 16], (double)v);
    v = blockReduceSum(s_trust, sbuf); if (tid == 0) atomicAdd(&g_acc[1 * 16], (double)v);
    v = blockReduceSum(s_perr, sbuf);  if (tid == 0) atomicAdd(&g_acc[2 * 16], (double)v);
    v = blockReduceSum(s_valid, sbuf); if (tid == 0) atomicAdd(&g_acc[3 * 16], (double)v);
    v = blockReduceSum(s_sign, sbuf);  if (tid == 0) atomicAdd(&g_acc[4 * 16], (double)v);
    v = blockReduceSum(s_mag, sbuf);   if (tid == 0) atomicAdd(&g_acc[5 * 16], (double)v);
    v = blockReduceSum(s_act, sbuf);   if (tid == 0) atomicAdd(&g_acc[6 * 16], (double)v);
    v = blockReduceSum(s_sx, sbuf);    if (tid == 0) atomicAdd(&g_acc[7 * 16], (double)v);
    v = blockReduceSum(s_sy, sbuf);    if (tid == 0) atomicAdd(&g_acc[8 * 16], (double)v);

    // --- finalize (last block) ---
    if (tid == 0) {
        __threadfence();
        int c = atomicAdd(&g_counter, 1);
        lastFlag = (c == TILE_BLOCKS - 1) ? 1 : 0;
    }
    __syncthreads();
    if (lastFlag && tid == 0) {
        __threadfence();
        double gtl = g_acc[0 * 16] / fmax(g_acc[1 * 16], 1.0);
        double photo = g_acc[2 * 16] / fmax(g_acc[3 * 16], 1.0);
        double n = fmax(g_acc[6 * 16], 1.0);
        double signmag = 0.3 * (g_acc[4 * 16] / n) + 0.7 * (g_acc[5 * 16] / n);
        double smooth = g_acc[7 * 16] / ((double)BB * HH * (WW - 1)) +
                        g_acc[8 * 16] / ((double)BB * (HH - 1) * WW);
        out[0] = (float)(1.0 * gtl + 1.0 * photo + 0.5 * signmag + 0.1 * smooth);
        g_counter = 0;
    }
}

// ---------------- launch ----------------
extern "C" void kernel_launch(void* const* d_in, const int* in_sizes, int n_in,
                              void* d_out, int out_size) {
    const float* pred  = (const float*)d_in[0];
    const float* gt    = (const float*)d_in[1];
    const float* conf  = (const float*)d_in[2];
    const float* occ   = (const float*)d_in[3];
    const float* left  = (const float*)d_in[4];
    const float* right = (const float*)d_in[5];
    float* out = (float*)d_out;

    downsample_kernel<<<(BB * H2 * (W2 / 2) + 255) / 256, 256>>>(left, right);
    ncc_kernel<<<BB * (H2 / 2), 480>>>();
    dim3 tb(16, 8), tg(WW / 64, HH / 8, BB);
    tile_kernel<<<tg, tb>>>(pred, gt, conf, occ, left, right, out);
}